// round 6
// baseline (speedup 1.0000x reference)
#include <cuda_runtime.h>

// ---------------------------------------------------------------------------
// Model_38225208935040: multi-region perturbed PINN forward.
//
// Algebraic collapse: mean over each symmetric perturbation grid of
// wave(base + delta) = Cd * wave(base), with
//   Cd_j = prod_d [ (1/s) * sum_i cos(lin_i * W1[d, j]) ]
// So 496 embedding evals/point -> 1 wave(base) + 3 precomputed 64-vectors.
//
// R6: warp-local Phase D. One warp owns one point; split-K in-warp with
// shfl_xor reduction; 2 block barriers total. No register cap (R4/R5 showed
// caps force spills that cost more than the occupancy buys).
// ---------------------------------------------------------------------------

#define PPB 8          // points per block (= warps per block)
#define NTHREADS 256
#define EPAD 260       // esh row stride (bank-conflict padding)
#define HPAD 68        // hsh row stride (16B-aligned quads)

// -------------------------- main fused kernel ------------------------------
__global__ void __launch_bounds__(NTHREADS) model_main_kernel(
    const float* __restrict__ x, const float* __restrict__ y, const float* __restrict__ t,
    const float* __restrict__ W1, const float* __restrict__ b1,
    const float* __restrict__ pwa, const float* __restrict__ pwb,
    const float* __restrict__ W2, const float* __restrict__ b2,
    const float* __restrict__ mW1, const float* __restrict__ mb1,
    const float* __restrict__ pmwa, const float* __restrict__ pmwb,
    const float* __restrict__ mW2, const float* __restrict__ pmb2,
    const float* __restrict__ W0, const float* __restrict__ b0,
    const float* __restrict__ pwa0, const float* __restrict__ pwb0,
    const float* __restrict__ Wh, const float* __restrict__ bh,
    const float* __restrict__ wah, const float* __restrict__ wbh,
    const float* __restrict__ Wf1, const float* __restrict__ bf1,
    const float* __restrict__ pwaf, const float* __restrict__ pwbf,
    const float* __restrict__ Wf2, const float* __restrict__ bf2,
    float* __restrict__ out, int npts)
{
    __shared__ float  cdsh[3][64];      // per-region Cd vectors
    __shared__ float4 swc[PPB][64];     // (w, Cd1*w, Cd2*w, Cd3*w)
    __shared__ float  esh[PPB][EPAD];   // mixed features e
    __shared__ float  hsh[PPB][HPAD];   // out-MLP hidden state

    const int tid = threadIdx.x;
    const int base_pt = blockIdx.x * PPB;

    // ---------------- Phase A0: Cd (symmetric-pair cosine sums) ------------
    if (tid < 192) {
        int r = tid >> 6;
        int j = tid & 63;
        const int   S[3] = {3, 5, 7};
        const float R[3] = {0.01f, 0.05f, 0.09f};
        int s = S[r];
        float rr = R[r];
        float inv = 1.0f / (float)s;
        float step = 2.0f * rr / (float)(s - 1);
        float prod = 1.0f;
        #pragma unroll
        for (int d = 0; d < 3; d++) {
            float w = W1[d * 64 + j];
            float c = 1.0f;                      // center sample (lin = 0)
            for (int i = 0; i < (s >> 1); i++)   // symmetric pairs
                c += 2.0f * __cosf((step * (float)i - rr) * w);
            prod *= c * inv;
        }
        cdsh[r][j] = prod;
    }
    __syncthreads();

    // ---------------- Phase A: base embedding pre-activation ---------------
    {
        const float wa = pwa[0], wb = pwb[0];
        #pragma unroll
        for (int it = 0; it < 2; it++) {
            int i  = tid + it * NTHREADS;
            int pt = i >> 6;
            int j  = i & 63;
            int n  = base_pt + pt;
            if (n >= npts) n = npts - 1;
            float xv = x[n], yv = y[n], tv = t[n];
            float z = fmaf(xv, W1[j], fmaf(yv, W1[64 + j], fmaf(tv, W1[128 + j], b1[j])));
            float sn, cn;
            __sincosf(z, &sn, &cn);
            float w = fmaf(wa, sn, wb * cn);
            swc[pt][j] = make_float4(w, cdsh[0][j] * w, cdsh[1][j] * w, cdsh[2][j] * w);
        }
    }
    __syncthreads();

    // ---------------- Phase B: 4-region GEMV vs W2 [64,256] ----------------
    // Thread owns column quad q for TWO points (pg, pg+4); each weight
    // float4 load feeds 32 FMAs.
    {
        const int q  = tid & 63;
        const int pg = tid >> 6;             // warp-uniform point group
        const float4* __restrict__ W2v = (const float4*)W2;   // [64][64] float4
        float4 a[2][4];                      // [pt][col]; components = regions
        #pragma unroll
        for (int p = 0; p < 2; p++)
            #pragma unroll
            for (int c = 0; c < 4; c++)
                a[p][c] = make_float4(0.f, 0.f, 0.f, 0.f);

        #pragma unroll 8
        for (int j = 0; j < 64; j++) {
            float4 w  = W2v[j * 64 + q];     // coalesced LDG.128
            float4 c0 = swc[pg][j];          // broadcast LDS.128
            float4 c1 = swc[pg + 4][j];
            a[0][0].x = fmaf(c0.x, w.x, a[0][0].x); a[0][0].y = fmaf(c0.y, w.x, a[0][0].y);
            a[0][0].z = fmaf(c0.z, w.x, a[0][0].z); a[0][0].w = fmaf(c0.w, w.x, a[0][0].w);
            a[0][1].x = fmaf(c0.x, w.y, a[0][1].x); a[0][1].y = fmaf(c0.y, w.y, a[0][1].y);
            a[0][1].z = fmaf(c0.z, w.y, a[0][1].z); a[0][1].w = fmaf(c0.w, w.y, a[0][1].w);
            a[0][2].x = fmaf(c0.x, w.z, a[0][2].x); a[0][2].y = fmaf(c0.y, w.z, a[0][2].y);
            a[0][2].z = fmaf(c0.z, w.z, a[0][2].z); a[0][2].w = fmaf(c0.w, w.z, a[0][2].w);
            a[0][3].x = fmaf(c0.x, w.w, a[0][3].x); a[0][3].y = fmaf(c0.y, w.w, a[0][3].y);
            a[0][3].z = fmaf(c0.z, w.w, a[0][3].z); a[0][3].w = fmaf(c0.w, w.w, a[0][3].w);
            a[1][0].x = fmaf(c1.x, w.x, a[1][0].x); a[1][0].y = fmaf(c1.y, w.x, a[1][0].y);
            a[1][0].z = fmaf(c1.z, w.x, a[1][0].z); a[1][0].w = fmaf(c1.w, w.x, a[1][0].w);
            a[1][1].x = fmaf(c1.x, w.y, a[1][1].x); a[1][1].y = fmaf(c1.y, w.y, a[1][1].y);
            a[1][1].z = fmaf(c1.z, w.y, a[1][1].z); a[1][1].w = fmaf(c1.w, w.y, a[1][1].w);
            a[1][2].x = fmaf(c1.x, w.z, a[1][2].x); a[1][2].y = fmaf(c1.y, w.z, a[1][2].y);
            a[1][2].z = fmaf(c1.z, w.z, a[1][2].z); a[1][2].w = fmaf(c1.w, w.z, a[1][2].w);
            a[1][3].x = fmaf(c1.x, w.w, a[1][3].x); a[1][3].y = fmaf(c1.y, w.w, a[1][3].y);
            a[1][3].z = fmaf(c1.z, w.w, a[1][3].z); a[1][3].w = fmaf(c1.w, w.w, a[1][3].w);
        }

        // ------------- Phase C: mixer (4 -> 8 -> 1), per column ------------
        const float4 b2q = ((const float4*)b2)[q];
        const float mwa = pmwa[0], mwb = pmwb[0], mb2v = pmb2[0];
        #pragma unroll
        for (int c = 0; c < 4; c++) {
            float bc = (c == 0) ? b2q.x : (c == 1) ? b2q.y : (c == 2) ? b2q.z : b2q.w;
            float s00 = a[0][c].x + bc, s01 = a[0][c].y + bc,
                  s02 = a[0][c].z + bc, s03 = a[0][c].w + bc;
            float s10 = a[1][c].x + bc, s11 = a[1][c].y + bc,
                  s12 = a[1][c].z + bc, s13 = a[1][c].w + bc;
            float e0 = mb2v, e1 = mb2v;
            #pragma unroll
            for (int h = 0; h < 8; h++) {
                float w0 = mW1[h], w1 = mW1[8 + h], w2 = mW1[16 + h], w3 = mW1[24 + h];
                float bb = mb1[h], m2 = mW2[h];
                float z0 = fmaf(s00, w0, fmaf(s01, w1, fmaf(s02, w2, fmaf(s03, w3, bb))));
                float z1 = fmaf(s10, w0, fmaf(s11, w1, fmaf(s12, w2, fmaf(s13, w3, bb))));
                float sn, cn;
                __sincosf(z0, &sn, &cn); e0 = fmaf(fmaf(mwa, sn, mwb * cn), m2, e0);
                __sincosf(z1, &sn, &cn); e1 = fmaf(fmaf(mwa, sn, mwb * cn), m2, e1);
            }
            esh[pg][4 * q + c]     = e0;
            esh[pg + 4][4 * q + c] = e1;
        }
    }
    __syncthreads();

    // ---------------- Phase D: out MLP, fully warp-local -------------------
    // Warp w owns point w. Within the warp: f4 = lane&15 (feature quad),
    // g = lane>>4 (k-half). Reduction via shfl_xor(16). No block barriers.
    {
        const int lane = tid & 31;
        const int wpt  = tid >> 5;          // this warp's point
        const int f4   = lane & 15;
        const int g    = lane >> 4;

        // ---- layer 0: 256 -> 64 (k split 2 x 128, in-warp) ----
        {
            const float4* __restrict__ W0v = (const float4*)W0;  // [256][16] f4
            float4 acc = {0,0,0,0};
            #pragma unroll 8
            for (int kk = 0; kk < 128; kk++) {
                int k = g * 128 + kk;
                float e  = esh[wpt][k];
                float4 w = W0v[k * 16 + f4];
                acc.x = fmaf(e, w.x, acc.x); acc.y = fmaf(e, w.y, acc.y);
                acc.z = fmaf(e, w.z, acc.z); acc.w = fmaf(e, w.w, acc.w);
            }
            acc.x += __shfl_xor_sync(0xFFFFFFFFu, acc.x, 16);
            acc.y += __shfl_xor_sync(0xFFFFFFFFu, acc.y, 16);
            acc.z += __shfl_xor_sync(0xFFFFFFFFu, acc.z, 16);
            acc.w += __shfl_xor_sync(0xFFFFFFFFu, acc.w, 16);
            if (g == 0) {
                const float lwa = pwa0[0], lwb = pwb0[0];
                float4 bq = ((const float4*)b0)[f4];
                float sn, cn;
                float4 hv;
                __sincosf(acc.x + bq.x, &sn, &cn); hv.x = fmaf(lwa, sn, lwb * cn);
                __sincosf(acc.y + bq.y, &sn, &cn); hv.y = fmaf(lwa, sn, lwb * cn);
                __sincosf(acc.z + bq.z, &sn, &cn); hv.z = fmaf(lwa, sn, lwb * cn);
                __sincosf(acc.w + bq.w, &sn, &cn); hv.w = fmaf(lwa, sn, lwb * cn);
                *(float4*)&hsh[wpt][4 * f4] = hv;
            }
            __syncwarp();
        }

        // ---- 3 hidden + final hidden: 64 -> 64 (k split 2 x 32) ----
        #pragma unroll 1
        for (int L = 0; L < 4; L++) {
            const float* __restrict__ Wl = (L < 3) ? (Wh + L * 4096) : Wf1;
            const float* __restrict__ bl = (L < 3) ? (bh + L * 64)   : bf1;
            const float  lwa = (L < 3) ? wah[L] : pwaf[0];
            const float  lwb = (L < 3) ? wbh[L] : pwbf[0];
            const float4* __restrict__ Wv = (const float4*)Wl;   // [64][16] f4
            float4 acc = {0,0,0,0};
            #pragma unroll 8
            for (int kk = 0; kk < 32; kk++) {
                int k = g * 32 + kk;
                float h  = hsh[wpt][k];
                float4 w = Wv[k * 16 + f4];
                acc.x = fmaf(h, w.x, acc.x); acc.y = fmaf(h, w.y, acc.y);
                acc.z = fmaf(h, w.z, acc.z); acc.w = fmaf(h, w.w, acc.w);
            }
            acc.x += __shfl_xor_sync(0xFFFFFFFFu, acc.x, 16);
            acc.y += __shfl_xor_sync(0xFFFFFFFFu, acc.y, 16);
            acc.z += __shfl_xor_sync(0xFFFFFFFFu, acc.z, 16);
            acc.w += __shfl_xor_sync(0xFFFFFFFFu, acc.w, 16);
            __syncwarp();                    // all reads of hsh done
            if (g == 0) {
                float4 bq = ((const float4*)bl)[f4];
                float sn, cn;
                float4 hv;
                __sincosf(acc.x + bq.x, &sn, &cn); hv.x = fmaf(lwa, sn, lwb * cn);
                __sincosf(acc.y + bq.y, &sn, &cn); hv.y = fmaf(lwa, sn, lwb * cn);
                __sincosf(acc.z + bq.z, &sn, &cn); hv.z = fmaf(lwa, sn, lwb * cn);
                __sincosf(acc.w + bq.w, &sn, &cn); hv.w = fmaf(lwa, sn, lwb * cn);
                *(float4*)&hsh[wpt][4 * f4] = hv;
            }
            __syncwarp();                    // writes visible to whole warp
        }

        // ---- output: 64 -> 3, 12 lanes, shuffle reduce ----
        if (lane < 12) {
            int f = lane >> 2, sub = lane & 3;
            float a = 0.f;
            #pragma unroll
            for (int i = 0; i < 16; i++) {
                int k = sub * 16 + i;
                a = fmaf(hsh[wpt][k], Wf2[k * 3 + f], a);
            }
            a += __shfl_xor_sync(0x00000FFFu, a, 1);
            a += __shfl_xor_sync(0x00000FFFu, a, 2);
            if (sub == 0) {
                int n = base_pt + wpt;
                if (n < npts) out[n * 3 + f] = a + bf2[f];
            }
        }
    }
}

// ---------------------------------------------------------------------------
extern "C" void kernel_launch(void* const* d_in, const int* in_sizes, int n_in,
                              void* d_out, int out_size) {
    const float* x    = (const float*)d_in[0];
    const float* y    = (const float*)d_in[1];
    const float* t    = (const float*)d_in[2];
    const float* W1   = (const float*)d_in[3];
    const float* b1   = (const float*)d_in[4];
    const float* wa   = (const float*)d_in[5];
    const float* wb   = (const float*)d_in[6];
    const float* W2   = (const float*)d_in[7];
    const float* b2   = (const float*)d_in[8];
    const float* mW1  = (const float*)d_in[9];
    const float* mb1  = (const float*)d_in[10];
    const float* mwa  = (const float*)d_in[11];
    const float* mwb  = (const float*)d_in[12];
    const float* mW2  = (const float*)d_in[13];
    const float* mb2  = (const float*)d_in[14];
    const float* W0   = (const float*)d_in[15];
    const float* b0   = (const float*)d_in[16];
    const float* wa0  = (const float*)d_in[17];
    const float* wb0  = (const float*)d_in[18];
    const float* Wh   = (const float*)d_in[19];
    const float* bh   = (const float*)d_in[20];
    const float* wah  = (const float*)d_in[21];
    const float* wbh  = (const float*)d_in[22];
    const float* Wf1  = (const float*)d_in[23];
    const float* bf1  = (const float*)d_in[24];
    const float* waf  = (const float*)d_in[25];
    const float* wbf  = (const float*)d_in[26];
    const float* Wf2  = (const float*)d_in[27];
    const float* bf2  = (const float*)d_in[28];
    float* out = (float*)d_out;

    int npts = in_sizes[0];
    int nblocks = (npts + PPB - 1) / PPB;

    model_main_kernel<<<nblocks, NTHREADS>>>(
        x, y, t, W1, b1, wa, wb, W2, b2,
        mW1, mb1, mwa, mwb, mW2, mb2,
        W0, b0, wa0, wb0, Wh, bh, wah, wbh,
        Wf1, bf1, waf, wbf, Wf2, bf2,
        out, npts);
}

// round 7
// speedup vs baseline: 1.1992x; 1.1992x over previous
#include <cuda_runtime.h>

// ---------------------------------------------------------------------------
// Model_38225208935040: multi-region perturbed PINN forward.
//
// Algebraic collapse: mean over each symmetric perturbation grid of
// wave(base + delta) = Cd * wave(base), with
//   Cd_j = prod_d [ (1/s) * sum_i cos(lin_i * W1[d, j]) ]
// So 496 embedding evals/point -> 1 wave(base) + 3 precomputed 64-vectors.
//
// R7 (on top of the R3 winner):
//  - Phase D: split-K 8, 4 points/thread -> per-block weight traffic 1x.
//  - wave(z) = A*sin(z+phi) (A, phi precomputed) -> MUFU halved everywhere.
// ---------------------------------------------------------------------------

#define PPB 8          // points per block
#define NTHREADS 256
#define EPAD 260       // esh row stride (bank-conflict padding)
#define HPAD 68        // hsh row stride

__device__ float g_Cd[3 * 64];
__device__ float g_wc[14];   // 7 (A, phi) pairs: emb, mix, out0, h0, h1, h2, outf

// -------------------------- setup: Cd + wave constants ---------------------
__global__ void setup_cd_kernel(const float* __restrict__ W1,
                                const float* __restrict__ ewa, const float* __restrict__ ewb,
                                const float* __restrict__ mwa, const float* __restrict__ mwb,
                                const float* __restrict__ wa0, const float* __restrict__ wb0,
                                const float* __restrict__ wah, const float* __restrict__ wbh,
                                const float* __restrict__ waf, const float* __restrict__ wbf) {
    int tid = threadIdx.x;
    if (tid < 192) {
        int r = tid >> 6;
        int j = tid & 63;
        const int   S[3] = {3, 5, 7};
        const float R[3] = {0.01f, 0.05f, 0.09f};
        int s = S[r];
        float rr = R[r];
        float inv = 1.0f / (float)s;
        float step = 2.0f * rr / (float)(s - 1);
        float prod = 1.0f;
        #pragma unroll
        for (int d = 0; d < 3; d++) {
            float w = W1[d * 64 + j];
            float c = 0.0f;
            for (int i = 0; i < s; i++) {
                float lin = -rr + step * (float)i;
                c += cosf(lin * w);
            }
            prod *= c * inv;
        }
        g_Cd[r * 64 + j] = prod;
    } else if (tid < 199) {
        int l = tid - 192;
        float a, b;
        switch (l) {
            case 0: a = ewa[0]; b = ewb[0]; break;
            case 1: a = mwa[0]; b = mwb[0]; break;
            case 2: a = wa0[0]; b = wb0[0]; break;
            case 3: a = wah[0]; b = wbh[0]; break;
            case 4: a = wah[1]; b = wbh[1]; break;
            case 5: a = wah[2]; b = wbh[2]; break;
            default: a = waf[0]; b = wbf[0]; break;
        }
        g_wc[2 * l]     = sqrtf(a * a + b * b);
        g_wc[2 * l + 1] = atan2f(b, a);
    }
}

// -------------------------- main fused kernel ------------------------------
__global__ void __launch_bounds__(NTHREADS) model_main_kernel(
    const float* __restrict__ x, const float* __restrict__ y, const float* __restrict__ t,
    const float* __restrict__ W1, const float* __restrict__ b1,
    const float* __restrict__ W2, const float* __restrict__ b2,
    const float* __restrict__ mW1, const float* __restrict__ mb1,
    const float* __restrict__ mW2, const float* __restrict__ pmb2,
    const float* __restrict__ W0, const float* __restrict__ b0,
    const float* __restrict__ Wh, const float* __restrict__ bh,
    const float* __restrict__ Wf1, const float* __restrict__ bf1,
    const float* __restrict__ Wf2, const float* __restrict__ bf2,
    float* __restrict__ out, int npts)
{
    __shared__ float4 swc[PPB][64];        // (w, Cd1*w, Cd2*w, Cd3*w)
    __shared__ float  esh[PPB][EPAD];      // mixed features e
    __shared__ float  hsh[PPB][HPAD];      // out-MLP hidden state
    __shared__ float4 pshare[8][PPB][16];  // split-K partials [group][pt][f-quad]

    const int tid = threadIdx.x;
    const int base_pt = blockIdx.x * PPB;

    // ---------------- Phase A: base embedding pre-activation ---------------
    {
        const float Ae = g_wc[0], pe = g_wc[1];
        #pragma unroll
        for (int it = 0; it < 2; it++) {
            int i  = tid + it * NTHREADS;
            int pt = i >> 6;
            int j  = i & 63;
            int n  = base_pt + pt;
            if (n >= npts) n = npts - 1;
            float xv = x[n], yv = y[n], tv = t[n];
            float z = fmaf(xv, W1[j], fmaf(yv, W1[64 + j], fmaf(tv, W1[128 + j], b1[j])));
            float w = Ae * __sinf(z + pe);
            swc[pt][j] = make_float4(w, g_Cd[j] * w, g_Cd[64 + j] * w, g_Cd[128 + j] * w);
        }
    }
    __syncthreads();

    // ---------------- Phase B: 4-region GEMV vs W2 [64,256] ----------------
    // Thread owns column quad q for TWO points (pg, pg+4); each weight
    // float4 load feeds 32 FMAs.
    {
        const int q  = tid & 63;
        const int pg = tid >> 6;             // warp-uniform point group
        const float4* __restrict__ W2v = (const float4*)W2;   // [64][64] float4
        float4 a[2][4];                      // [pt][col]; components = regions
        #pragma unroll
        for (int p = 0; p < 2; p++)
            #pragma unroll
            for (int c = 0; c < 4; c++)
                a[p][c] = make_float4(0.f, 0.f, 0.f, 0.f);

        #pragma unroll 8
        for (int j = 0; j < 64; j++) {
            float4 w  = W2v[j * 64 + q];     // coalesced LDG.128
            float4 c0 = swc[pg][j];          // broadcast LDS.128
            float4 c1 = swc[pg + 4][j];
            a[0][0].x = fmaf(c0.x, w.x, a[0][0].x); a[0][0].y = fmaf(c0.y, w.x, a[0][0].y);
            a[0][0].z = fmaf(c0.z, w.x, a[0][0].z); a[0][0].w = fmaf(c0.w, w.x, a[0][0].w);
            a[0][1].x = fmaf(c0.x, w.y, a[0][1].x); a[0][1].y = fmaf(c0.y, w.y, a[0][1].y);
            a[0][1].z = fmaf(c0.z, w.y, a[0][1].z); a[0][1].w = fmaf(c0.w, w.y, a[0][1].w);
            a[0][2].x = fmaf(c0.x, w.z, a[0][2].x); a[0][2].y = fmaf(c0.y, w.z, a[0][2].y);
            a[0][2].z = fmaf(c0.z, w.z, a[0][2].z); a[0][2].w = fmaf(c0.w, w.z, a[0][2].w);
            a[0][3].x = fmaf(c0.x, w.w, a[0][3].x); a[0][3].y = fmaf(c0.y, w.w, a[0][3].y);
            a[0][3].z = fmaf(c0.z, w.w, a[0][3].z); a[0][3].w = fmaf(c0.w, w.w, a[0][3].w);
            a[1][0].x = fmaf(c1.x, w.x, a[1][0].x); a[1][0].y = fmaf(c1.y, w.x, a[1][0].y);
            a[1][0].z = fmaf(c1.z, w.x, a[1][0].z); a[1][0].w = fmaf(c1.w, w.x, a[1][0].w);
            a[1][1].x = fmaf(c1.x, w.y, a[1][1].x); a[1][1].y = fmaf(c1.y, w.y, a[1][1].y);
            a[1][1].z = fmaf(c1.z, w.y, a[1][1].z); a[1][1].w = fmaf(c1.w, w.y, a[1][1].w);
            a[1][2].x = fmaf(c1.x, w.z, a[1][2].x); a[1][2].y = fmaf(c1.y, w.z, a[1][2].y);
            a[1][2].z = fmaf(c1.z, w.z, a[1][2].z); a[1][2].w = fmaf(c1.w, w.z, a[1][2].w);
            a[1][3].x = fmaf(c1.x, w.w, a[1][3].x); a[1][3].y = fmaf(c1.y, w.w, a[1][3].y);
            a[1][3].z = fmaf(c1.z, w.w, a[1][3].z); a[1][3].w = fmaf(c1.w, w.w, a[1][3].w);
        }

        // ------------- Phase C: mixer (4 -> 8 -> 1), per column ------------
        const float4 b2q = ((const float4*)b2)[q];
        const float Am = g_wc[2], pm = g_wc[3], mb2v = pmb2[0];
        #pragma unroll
        for (int c = 0; c < 4; c++) {
            float bc = (c == 0) ? b2q.x : (c == 1) ? b2q.y : (c == 2) ? b2q.z : b2q.w;
            float s00 = a[0][c].x + bc, s01 = a[0][c].y + bc,
                  s02 = a[0][c].z + bc, s03 = a[0][c].w + bc;
            float s10 = a[1][c].x + bc, s11 = a[1][c].y + bc,
                  s12 = a[1][c].z + bc, s13 = a[1][c].w + bc;
            float e0 = mb2v, e1 = mb2v;
            #pragma unroll
            for (int h = 0; h < 8; h++) {
                float w0 = mW1[h], w1 = mW1[8 + h], w2 = mW1[16 + h], w3 = mW1[24 + h];
                float bb = mb1[h] + pm;          // fold phase into bias
                float m2A = Am * mW2[h];         // fold amplitude into m2
                float z0 = fmaf(s00, w0, fmaf(s01, w1, fmaf(s02, w2, fmaf(s03, w3, bb))));
                float z1 = fmaf(s10, w0, fmaf(s11, w1, fmaf(s12, w2, fmaf(s13, w3, bb))));
                e0 = fmaf(__sinf(z0), m2A, e0);
                e1 = fmaf(__sinf(z1), m2A, e1);
            }
            esh[pg][4 * q + c]     = e0;
            esh[pg + 4][4 * q + c] = e1;
        }
    }
    __syncthreads();

    // ---------------- Phase D: out MLP, split-K 8, 4 pts/thread ------------
    // Mapping: f4 = tid&15 (feature quad), pp = (tid>>4)&1 (point parity:
    // points pp, pp+2, pp+4, pp+6), g = tid>>5 (k-group, warp-uniform).
    // Each warp reads a DISTINCT 1/8 of the weight rows -> 1x traffic.
    const int f4 = tid & 15;
    const int pp = (tid >> 4) & 1;
    const int g  = tid >> 5;
    const float* ps = (const float*)pshare;   // flat [g][pt][64]

    // layer 0: 256 -> 64 (k split 8 x 32)
    {
        const float4* __restrict__ W0v = (const float4*)W0;  // [256][16] float4
        float4 ac0 = {0,0,0,0}, ac1 = {0,0,0,0}, ac2 = {0,0,0,0}, ac3 = {0,0,0,0};
        #pragma unroll 8
        for (int kk = 0; kk < 32; kk++) {
            int k = g * 32 + kk;
            float4 w = W0v[k * 16 + f4];
            float e0 = esh[pp][k];
            float e1 = esh[pp + 2][k];
            float e2 = esh[pp + 4][k];
            float e3 = esh[pp + 6][k];
            ac0.x = fmaf(e0, w.x, ac0.x); ac0.y = fmaf(e0, w.y, ac0.y);
            ac0.z = fmaf(e0, w.z, ac0.z); ac0.w = fmaf(e0, w.w, ac0.w);
            ac1.x = fmaf(e1, w.x, ac1.x); ac1.y = fmaf(e1, w.y, ac1.y);
            ac1.z = fmaf(e1, w.z, ac1.z); ac1.w = fmaf(e1, w.w, ac1.w);
            ac2.x = fmaf(e2, w.x, ac2.x); ac2.y = fmaf(e2, w.y, ac2.y);
            ac2.z = fmaf(e2, w.z, ac2.z); ac2.w = fmaf(e2, w.w, ac2.w);
            ac3.x = fmaf(e3, w.x, ac3.x); ac3.y = fmaf(e3, w.y, ac3.y);
            ac3.z = fmaf(e3, w.z, ac3.z); ac3.w = fmaf(e3, w.w, ac3.w);
        }
        pshare[g][pp][f4]     = ac0;
        pshare[g][pp + 2][f4] = ac1;
        pshare[g][pp + 4][f4] = ac2;
        pshare[g][pp + 6][f4] = ac3;
        __syncthreads();
        const float A0 = g_wc[4], p0 = g_wc[5];
        #pragma unroll
        for (int it = 0; it < 2; it++) {
            int i = tid + it * NTHREADS;
            int ptR = i >> 6, f = i & 63;
            float a = b0[f];
            #pragma unroll
            for (int G = 0; G < 8; G++)
                a += ps[(G * PPB + ptR) * 64 + f];
            hsh[ptR][f] = A0 * __sinf(a + p0);
        }
        __syncthreads();
    }

    // 3 hidden layers + final hidden: 64 -> 64 with wave (k split 8 x 8)
    #pragma unroll 1
    for (int L = 0; L < 4; L++) {
        const float* __restrict__ Wl = (L < 3) ? (Wh + L * 4096) : Wf1;
        const float* __restrict__ bl = (L < 3) ? (bh + L * 64)   : bf1;
        const float  AL = g_wc[6 + 2 * L];
        const float  pL = g_wc[7 + 2 * L];
        const float4* __restrict__ Wv = (const float4*)Wl;   // [64][16] float4
        float4 ac0 = {0,0,0,0}, ac1 = {0,0,0,0}, ac2 = {0,0,0,0}, ac3 = {0,0,0,0};
        #pragma unroll
        for (int kk = 0; kk < 8; kk++) {
            int k = g * 8 + kk;
            float4 w = Wv[k * 16 + f4];
            float h0 = hsh[pp][k];
            float h1 = hsh[pp + 2][k];
            float h2 = hsh[pp + 4][k];
            float h3 = hsh[pp + 6][k];
            ac0.x = fmaf(h0, w.x, ac0.x); ac0.y = fmaf(h0, w.y, ac0.y);
            ac0.z = fmaf(h0, w.z, ac0.z); ac0.w = fmaf(h0, w.w, ac0.w);
            ac1.x = fmaf(h1, w.x, ac1.x); ac1.y = fmaf(h1, w.y, ac1.y);
            ac1.z = fmaf(h1, w.z, ac1.z); ac1.w = fmaf(h1, w.w, ac1.w);
            ac2.x = fmaf(h2, w.x, ac2.x); ac2.y = fmaf(h2, w.y, ac2.y);
            ac2.z = fmaf(h2, w.z, ac2.z); ac2.w = fmaf(h2, w.w, ac2.w);
            ac3.x = fmaf(h3, w.x, ac3.x); ac3.y = fmaf(h3, w.y, ac3.y);
            ac3.z = fmaf(h3, w.z, ac3.z); ac3.w = fmaf(h3, w.w, ac3.w);
        }
        pshare[g][pp][f4]     = ac0;
        pshare[g][pp + 2][f4] = ac1;
        pshare[g][pp + 4][f4] = ac2;
        pshare[g][pp + 6][f4] = ac3;
        __syncthreads();               // partials visible; all hsh reads done
        #pragma unroll
        for (int it = 0; it < 2; it++) {
            int i = tid + it * NTHREADS;
            int ptR = i >> 6, f = i & 63;
            float a = bl[f];
            #pragma unroll
            for (int G = 0; G < 8; G++)
                a += ps[(G * PPB + ptR) * 64 + f];
            hsh[ptR][f] = AL * __sinf(a + pL);   // safe: reads done pre-barrier
        }
        __syncthreads();               // hsh writes visible for next layer
    }

    // output: 64 -> 3
    if (tid < PPB * 3) {
        int pt = tid / 3, f = tid % 3;
        int n = base_pt + pt;
        if (n < npts) {
            float a0 = 0.f, a1 = 0.f, a2 = 0.f, a3 = 0.f;
            #pragma unroll
            for (int i = 0; i < 16; i++) {
                a0 = fmaf(hsh[pt][4 * i + 0], Wf2[(4 * i + 0) * 3 + f], a0);
                a1 = fmaf(hsh[pt][4 * i + 1], Wf2[(4 * i + 1) * 3 + f], a1);
                a2 = fmaf(hsh[pt][4 * i + 2], Wf2[(4 * i + 2) * 3 + f], a2);
                a3 = fmaf(hsh[pt][4 * i + 3], Wf2[(4 * i + 3) * 3 + f], a3);
            }
            out[n * 3 + f] = bf2[f] + (a0 + a1) + (a2 + a3);
        }
    }
}

// ---------------------------------------------------------------------------
extern "C" void kernel_launch(void* const* d_in, const int* in_sizes, int n_in,
                              void* d_out, int out_size) {
    const float* x    = (const float*)d_in[0];
    const float* y    = (const float*)d_in[1];
    const float* t    = (const float*)d_in[2];
    const float* W1   = (const float*)d_in[3];
    const float* b1   = (const float*)d_in[4];
    const float* wa   = (const float*)d_in[5];
    const float* wb   = (const float*)d_in[6];
    const float* W2   = (const float*)d_in[7];
    const float* b2   = (const float*)d_in[8];
    const float* mW1  = (const float*)d_in[9];
    const float* mb1  = (const float*)d_in[10];
    const float* mwa  = (const float*)d_in[11];
    const float* mwb  = (const float*)d_in[12];
    const float* mW2  = (const float*)d_in[13];
    const float* mb2  = (const float*)d_in[14];
    const float* W0   = (const float*)d_in[15];
    const float* b0   = (const float*)d_in[16];
    const float* wa0  = (const float*)d_in[17];
    const float* wb0  = (const float*)d_in[18];
    const float* Wh   = (const float*)d_in[19];
    const float* bh   = (const float*)d_in[20];
    const float* wah  = (const float*)d_in[21];
    const float* wbh  = (const float*)d_in[22];
    const float* Wf1  = (const float*)d_in[23];
    const float* bf1  = (const float*)d_in[24];
    const float* waf  = (const float*)d_in[25];
    const float* wbf  = (const float*)d_in[26];
    const float* Wf2  = (const float*)d_in[27];
    const float* bf2  = (const float*)d_in[28];
    float* out = (float*)d_out;

    int npts = in_sizes[0];
    int nblocks = (npts + PPB - 1) / PPB;

    setup_cd_kernel<<<1, 256>>>(W1, wa, wb, mwa, mwb, wa0, wb0, wah, wbh, waf, wbf);
    model_main_kernel<<<nblocks, NTHREADS>>>(
        x, y, t, W1, b1, W2, b2,
        mW1, mb1, mW2, mb2,
        W0, b0, Wh, bh,
        Wf1, bf1, Wf2, bf2,
        out, npts);
}

// round 8
// speedup vs baseline: 1.4202x; 1.1843x over previous
#include <cuda_runtime.h>

// ---------------------------------------------------------------------------
// Model_38225208935040: multi-region perturbed PINN forward.
//
// Algebraic collapse: mean over each symmetric perturbation grid of
// wave(base + delta) = Cd * wave(base), with
//   Cd_j = prod_d [ (1/s) * sum_i cos(lin_i * W1[d, j]) ]
// So 496 embedding evals/point -> 1 wave(base) + 3 precomputed 64-vectors.
//
// R8 (on top of the R7 winner):
//  - All GEMV inner loops use packed fma.rn.f32x2 (FFMA2): 2 fp32 FMAs per
//    fma-pipe slot -> halves the fma-pipe floor of the dominant phases.
//  - Cd + phase-shift wave constants computed in-kernel (setup launch gone).
// ---------------------------------------------------------------------------

#define PPB 8          // points per block
#define NTHREADS 256
#define EPAD 260       // esh row stride (bank-conflict padding)
#define HPAD 68        // hsh row stride

typedef unsigned long long ull;

__device__ __forceinline__ ull packf2(float lo, float hi) {
    ull d;
    asm("mov.b64 %0, {%1, %2};" : "=l"(d)
        : "r"(__float_as_uint(lo)), "r"(__float_as_uint(hi)));
    return d;
}
__device__ __forceinline__ void ffma2(ull& d, ull a, ull b) {
    asm("fma.rn.f32x2 %0, %1, %2, %0;" : "+l"(d) : "l"(a), "l"(b));
}
__device__ __forceinline__ float2 unpackf2(ull v) {
    unsigned int lo, hi;
    asm("mov.b64 {%0, %1}, %2;" : "=r"(lo), "=r"(hi) : "l"(v));
    return make_float2(__uint_as_float(lo), __uint_as_float(hi));
}

// -------------------------- main fused kernel ------------------------------
__global__ void __launch_bounds__(NTHREADS) model_main_kernel(
    const float* __restrict__ x, const float* __restrict__ y, const float* __restrict__ t,
    const float* __restrict__ W1, const float* __restrict__ b1,
    const float* __restrict__ ewa, const float* __restrict__ ewb,
    const float* __restrict__ W2, const float* __restrict__ b2,
    const float* __restrict__ mW1, const float* __restrict__ mb1,
    const float* __restrict__ mwa, const float* __restrict__ mwb,
    const float* __restrict__ mW2, const float* __restrict__ pmb2,
    const float* __restrict__ W0, const float* __restrict__ b0,
    const float* __restrict__ wa0, const float* __restrict__ wb0,
    const float* __restrict__ Wh, const float* __restrict__ bh,
    const float* __restrict__ wah, const float* __restrict__ wbh,
    const float* __restrict__ Wf1, const float* __restrict__ bf1,
    const float* __restrict__ waf, const float* __restrict__ wbf,
    const float* __restrict__ Wf2, const float* __restrict__ bf2,
    float* __restrict__ out, int npts)
{
    __shared__ float  cdsh[3][64];         // per-region Cd vectors
    __shared__ float  wcsh[14];            // 7 (A, phi) pairs
    __shared__ float4 swc[PPB][64];        // (w, Cd1*w, Cd2*w, Cd3*w)
    __shared__ float  esh[PPB][EPAD];      // mixed features e
    __shared__ float  hsh[PPB][HPAD];      // out-MLP hidden state
    __shared__ float4 pshare[8][PPB][16];  // split-K partials [group][pt][f-quad]

    const int tid = threadIdx.x;
    const int base_pt = blockIdx.x * PPB;

    // ---------------- Phase A0: Cd + wave constants ------------------------
    if (tid < 192) {
        int r = tid >> 6;
        int j = tid & 63;
        const int   S[3] = {3, 5, 7};
        const float R[3] = {0.01f, 0.05f, 0.09f};
        int s = S[r];
        float rr = R[r];
        float inv = 1.0f / (float)s;
        float step = 2.0f * rr / (float)(s - 1);
        float prod = 1.0f;
        #pragma unroll
        for (int d = 0; d < 3; d++) {
            float w = W1[d * 64 + j];
            float c = 1.0f;                      // center sample (lin = 0)
            for (int i = 0; i < (s >> 1); i++)   // symmetric pairs
                c += 2.0f * __cosf((step * (float)i - rr) * w);
            prod *= c * inv;
        }
        cdsh[r][j] = prod;
    } else if (tid < 199) {
        int l = tid - 192;
        float a, b;
        switch (l) {
            case 0: a = ewa[0]; b = ewb[0]; break;
            case 1: a = mwa[0]; b = mwb[0]; break;
            case 2: a = wa0[0]; b = wb0[0]; break;
            case 3: a = wah[0]; b = wbh[0]; break;
            case 4: a = wah[1]; b = wbh[1]; break;
            case 5: a = wah[2]; b = wbh[2]; break;
            default: a = waf[0]; b = wbf[0]; break;
        }
        wcsh[2 * l]     = sqrtf(a * a + b * b);
        wcsh[2 * l + 1] = atan2f(b, a);
    }
    __syncthreads();

    // ---------------- Phase A: base embedding pre-activation ---------------
    {
        const float Ae = wcsh[0], pe = wcsh[1];
        #pragma unroll
        for (int it = 0; it < 2; it++) {
            int i  = tid + it * NTHREADS;
            int pt = i >> 6;
            int j  = i & 63;
            int n  = base_pt + pt;
            if (n >= npts) n = npts - 1;
            float xv = x[n], yv = y[n], tv = t[n];
            float z = fmaf(xv, W1[j], fmaf(yv, W1[64 + j], fmaf(tv, W1[128 + j], b1[j])));
            float w = Ae * __sinf(z + pe);
            swc[pt][j] = make_float4(w, cdsh[0][j] * w, cdsh[1][j] * w, cdsh[2][j] * w);
        }
    }
    __syncthreads();

    // ---------------- Phase B: 4-region GEMV vs W2 [64,256], FFMA2 ---------
    // Thread owns column quad q for TWO points (pg, pg+4).
    // A[p][c][h]: packed region sums; h=0 -> (r0,r1), h=1 -> (r2,r3).
    {
        const int q  = tid & 63;
        const int pg = tid >> 6;             // warp-uniform point group
        const float4* __restrict__ W2v = (const float4*)W2;   // [64][64] float4
        ull A[2][4][2];
        #pragma unroll
        for (int p = 0; p < 2; p++)
            #pragma unroll
            for (int c = 0; c < 4; c++) {
                A[p][c][0] = 0ull; A[p][c][1] = 0ull;
            }

        #pragma unroll 8
        for (int j = 0; j < 64; j++) {
            float4 w  = W2v[j * 64 + q];     // coalesced LDG.128
            float4 c0 = swc[pg][j];          // broadcast LDS.128
            float4 c1 = swc[pg + 4][j];
            ull c0lo = packf2(c0.x, c0.y), c0hi = packf2(c0.z, c0.w);
            ull c1lo = packf2(c1.x, c1.y), c1hi = packf2(c1.z, c1.w);
            ull wx = packf2(w.x, w.x);
            ffma2(A[0][0][0], c0lo, wx); ffma2(A[0][0][1], c0hi, wx);
            ffma2(A[1][0][0], c1lo, wx); ffma2(A[1][0][1], c1hi, wx);
            ull wy = packf2(w.y, w.y);
            ffma2(A[0][1][0], c0lo, wy); ffma2(A[0][1][1], c0hi, wy);
            ffma2(A[1][1][0], c1lo, wy); ffma2(A[1][1][1], c1hi, wy);
            ull wz = packf2(w.z, w.z);
            ffma2(A[0][2][0], c0lo, wz); ffma2(A[0][2][1], c0hi, wz);
            ffma2(A[1][2][0], c1lo, wz); ffma2(A[1][2][1], c1hi, wz);
            ull ww = packf2(w.w, w.w);
            ffma2(A[0][3][0], c0lo, ww); ffma2(A[0][3][1], c0hi, ww);
            ffma2(A[1][3][0], c1lo, ww); ffma2(A[1][3][1], c1hi, ww);
        }

        // ------------- Phase C: mixer (4 -> 8 -> 1), per column ------------
        const float4 b2q = ((const float4*)b2)[q];
        const float Am = wcsh[2], pm = wcsh[3], mb2v = pmb2[0];
        #pragma unroll
        for (int c = 0; c < 4; c++) {
            float bc = (c == 0) ? b2q.x : (c == 1) ? b2q.y : (c == 2) ? b2q.z : b2q.w;
            float2 r01p0 = unpackf2(A[0][c][0]);
            float2 r23p0 = unpackf2(A[0][c][1]);
            float2 r01p1 = unpackf2(A[1][c][0]);
            float2 r23p1 = unpackf2(A[1][c][1]);
            float s00 = r01p0.x + bc, s01 = r01p0.y + bc,
                  s02 = r23p0.x + bc, s03 = r23p0.y + bc;
            float s10 = r01p1.x + bc, s11 = r01p1.y + bc,
                  s12 = r23p1.x + bc, s13 = r23p1.y + bc;
            float e0 = mb2v, e1 = mb2v;
            #pragma unroll
            for (int h = 0; h < 8; h++) {
                float w0 = mW1[h], w1 = mW1[8 + h], w2 = mW1[16 + h], w3 = mW1[24 + h];
                float bb = mb1[h] + pm;          // fold phase into bias
                float m2A = Am * mW2[h];         // fold amplitude into m2
                float z0 = fmaf(s00, w0, fmaf(s01, w1, fmaf(s02, w2, fmaf(s03, w3, bb))));
                float z1 = fmaf(s10, w0, fmaf(s11, w1, fmaf(s12, w2, fmaf(s13, w3, bb))));
                e0 = fmaf(__sinf(z0), m2A, e0);
                e1 = fmaf(__sinf(z1), m2A, e1);
            }
            esh[pg][4 * q + c]     = e0;
            esh[pg + 4][4 * q + c] = e1;
        }
    }
    __syncthreads();

    // ---------------- Phase D: out MLP, split-K 8, 4 pts/thread, FFMA2 -----
    // f4 = tid&15 (feature quad), pp = (tid>>4)&1 (points pp,pp+2,pp+4,pp+6),
    // g = tid>>5 (k-group, warp-uniform). Weight traffic = 1x per block.
    const int f4 = tid & 15;
    const int pp = (tid >> 4) & 1;
    const int g  = tid >> 5;
    const float* ps = (const float*)pshare;   // flat [g][pt][64]

    // layer 0: 256 -> 64 (k split 8 x 32)
    {
        const float4* __restrict__ W0v = (const float4*)W0;  // [256][16] float4
        ull acc[4][2];
        #pragma unroll
        for (int p = 0; p < 4; p++) { acc[p][0] = 0ull; acc[p][1] = 0ull; }
        #pragma unroll 8
        for (int kk = 0; kk < 32; kk++) {
            int k = g * 32 + kk;
            float4 w = W0v[k * 16 + f4];
            ull wlo = packf2(w.x, w.y), whi = packf2(w.z, w.w);
            #pragma unroll
            for (int p = 0; p < 4; p++) {
                float e = esh[pp + 2 * p][k];
                ull ep = packf2(e, e);
                ffma2(acc[p][0], wlo, ep);
                ffma2(acc[p][1], whi, ep);
            }
        }
        #pragma unroll
        for (int p = 0; p < 4; p++) {
            float2 lo = unpackf2(acc[p][0]);
            float2 hi = unpackf2(acc[p][1]);
            pshare[g][pp + 2 * p][f4] = make_float4(lo.x, lo.y, hi.x, hi.y);
        }
        __syncthreads();
        const float A0 = wcsh[4], p0 = wcsh[5];
        #pragma unroll
        for (int it = 0; it < 2; it++) {
            int i = tid + it * NTHREADS;
            int ptR = i >> 6, f = i & 63;
            float a = b0[f];
            #pragma unroll
            for (int G = 0; G < 8; G++)
                a += ps[(G * PPB + ptR) * 64 + f];
            hsh[ptR][f] = A0 * __sinf(a + p0);
        }
        __syncthreads();
    }

    // 3 hidden layers + final hidden: 64 -> 64 with wave (k split 8 x 8)
    #pragma unroll 1
    for (int L = 0; L < 4; L++) {
        const float* __restrict__ Wl = (L < 3) ? (Wh + L * 4096) : Wf1;
        const float* __restrict__ bl = (L < 3) ? (bh + L * 64)   : bf1;
        const float  AL = wcsh[6 + 2 * L];
        const float  pL = wcsh[7 + 2 * L];
        const float4* __restrict__ Wv = (const float4*)Wl;   // [64][16] float4
        ull acc[4][2];
        #pragma unroll
        for (int p = 0; p < 4; p++) { acc[p][0] = 0ull; acc[p][1] = 0ull; }
        #pragma unroll
        for (int kk = 0; kk < 8; kk++) {
            int k = g * 8 + kk;
            float4 w = Wv[k * 16 + f4];
            ull wlo = packf2(w.x, w.y), whi = packf2(w.z, w.w);
            #pragma unroll
            for (int p = 0; p < 4; p++) {
                float h = hsh[pp + 2 * p][k];
                ull hp = packf2(h, h);
                ffma2(acc[p][0], wlo, hp);
                ffma2(acc[p][1], whi, hp);
            }
        }
        #pragma unroll
        for (int p = 0; p < 4; p++) {
            float2 lo = unpackf2(acc[p][0]);
            float2 hi = unpackf2(acc[p][1]);
            pshare[g][pp + 2 * p][f4] = make_float4(lo.x, lo.y, hi.x, hi.y);
        }
        __syncthreads();               // partials visible; all hsh reads done
        #pragma unroll
        for (int it = 0; it < 2; it++) {
            int i = tid + it * NTHREADS;
            int ptR = i >> 6, f = i & 63;
            float a = bl[f];
            #pragma unroll
            for (int G = 0; G < 8; G++)
                a += ps[(G * PPB + ptR) * 64 + f];
            hsh[ptR][f] = AL * __sinf(a + pL);   // safe: reads done pre-barrier
        }
        __syncthreads();               // hsh writes visible for next layer
    }

    // output: 64 -> 3
    if (tid < PPB * 3) {
        int pt = tid / 3, f = tid % 3;
        int n = base_pt + pt;
        if (n < npts) {
            float a0 = 0.f, a1 = 0.f, a2 = 0.f, a3 = 0.f;
            #pragma unroll
            for (int i = 0; i < 16; i++) {
                a0 = fmaf(hsh[pt][4 * i + 0], Wf2[(4 * i + 0) * 3 + f], a0);
                a1 = fmaf(hsh[pt][4 * i + 1], Wf2[(4 * i + 1) * 3 + f], a1);
                a2 = fmaf(hsh[pt][4 * i + 2], Wf2[(4 * i + 2) * 3 + f], a2);
                a3 = fmaf(hsh[pt][4 * i + 3], Wf2[(4 * i + 3) * 3 + f], a3);
            }
            out[n * 3 + f] = bf2[f] + (a0 + a1) + (a2 + a3);
        }
    }
}

// ---------------------------------------------------------------------------
extern "C" void kernel_launch(void* const* d_in, const int* in_sizes, int n_in,
                              void* d_out, int out_size) {
    const float* x    = (const float*)d_in[0];
    const float* y    = (const float*)d_in[1];
    const float* t    = (const float*)d_in[2];
    const float* W1   = (const float*)d_in[3];
    const float* b1   = (const float*)d_in[4];
    const float* wa   = (const float*)d_in[5];
    const float* wb   = (const float*)d_in[6];
    const float* W2   = (const float*)d_in[7];
    const float* b2   = (const float*)d_in[8];
    const float* mW1  = (const float*)d_in[9];
    const float* mb1  = (const float*)d_in[10];
    const float* mwa  = (const float*)d_in[11];
    const float* mwb  = (const float*)d_in[12];
    const float* mW2  = (const float*)d_in[13];
    const float* mb2  = (const float*)d_in[14];
    const float* W0   = (const float*)d_in[15];
    const float* b0   = (const float*)d_in[16];
    const float* wa0  = (const float*)d_in[17];
    const float* wb0  = (const float*)d_in[18];
    const float* Wh   = (const float*)d_in[19];
    const float* bh   = (const float*)d_in[20];
    const float* wah  = (const float*)d_in[21];
    const float* wbh  = (const float*)d_in[22];
    const float* Wf1  = (const float*)d_in[23];
    const float* bf1  = (const float*)d_in[24];
    const float* waf  = (const float*)d_in[25];
    const float* wbf  = (const float*)d_in[26];
    const float* Wf2  = (const float*)d_in[27];
    const float* bf2  = (const float*)d_in[28];
    float* out = (float*)d_out;

    int npts = in_sizes[0];
    int nblocks = (npts + PPB - 1) / PPB;

    model_main_kernel<<<nblocks, NTHREADS>>>(
        x, y, t, W1, b1, wa, wb, W2, b2,
        mW1, mb1, mwa, mwb, mW2, mb2,
        W0, b0, wa0, wb0, Wh, bh, wah, wbh,
        Wf1, bf1, waf, wbf, Wf2, bf2,
        out, npts);
}